// round 14
// baseline (speedup 1.0000x reference)
#include <cuda_runtime.h>
#include <cuda_bf16.h>
#include <cstdint>

// ---------------- problem constants ----------------
#define NV   20000
#define KPV  8
#define MKP  (NV * KPV)
#define NE   320000
#define KPD  4
#define SD   300
#define SDP  320            // K=300 padded to 64-mult (320 = 5*64)
#define NP3  384            // N padded for B (3 x 128 tiles)
#define NU   303            // u GEMM N: 300 (Wf') + 3 (Wh)
#define USTR 320            // u row stride
#define TIT  3
#define NC   4

typedef __nv_bfloat16 bf16;

// ---------------- scratch ----------------
__device__ float g_h0[MKP * 64];
__device__ float g_h1[MKP * 128];
__device__ float g_kpmax[NV * SD];
__device__ float g_sA[NV * SD];
__device__ float g_sB[NV * SD];
__device__ float g_u[NV * USTR];        // cols 0..299 = u, 300..302 = dx
__device__ float g_aggr[NV * SD];
__device__ float g_c1[NV * 64];
__device__ float g_l1all[NV * 256];
__device__ float g_l2all[NV * 256];
__device__ float g_cbias[TIT * NU];     // [bf | bh] per iteration
// weight splits (bf16 hi/lo), K padded
__device__ bf16 g_wi1h[64 * 128],        g_wi1l[64 * 128];
__device__ bf16 g_wi2h[128 * NP3],       g_wi2l[128 * NP3];
__device__ bf16 g_wah[SDP * NP3],        g_wal[SDP * NP3];
__device__ bf16 g_wfph[TIT * SDP * NP3], g_wfpl[TIT * SDP * NP3];  // [Wf' | Wh]
__device__ bf16 g_wgh[TIT * SDP * NP3],  g_wgl[TIT * SDP * NP3];
__device__ bf16 g_wc1h[SDP * 64],        g_wc1l[SDP * 64];
__device__ bf16 g_wl1h[NC * SDP * 64],   g_wl1l[NC * SDP * 64];
__device__ bf16 g_wl2h[NC * 64 * 64],    g_wl2l[NC * 64 * 64];
// CSR
__device__ int g_counts[NV + 1];
__device__ int g_offs[NV + 1];
__device__ int g_cursor[NV];
__device__ int g_sortedSrc[NE];

// ---------------- helpers ----------------
__device__ __forceinline__ uint32_t smem_u32(const void* p) {
    uint32_t a;
    asm("{ .reg .u64 t; cvta.to.shared.u64 t, %1; cvt.u32.u64 %0, t; }" : "=r"(a) : "l"(p));
    return a;
}
__device__ __forceinline__ void split2(float x, bf16& h, bf16& l) {
    h = __float2bfloat16(x);
    l = __float2bfloat16(x - __bfloat162float(h));
}

#define LDSM_X4(r, addr) \
    asm volatile("ldmatrix.sync.aligned.m8n8.x4.shared.b16 {%0,%1,%2,%3}, [%4];" \
                 : "=r"((r)[0]), "=r"((r)[1]), "=r"((r)[2]), "=r"((r)[3]) : "r"(addr))
#define LDSM_X4T(r, addr) \
    asm volatile("ldmatrix.sync.aligned.m8n8.x4.trans.shared.b16 {%0,%1,%2,%3}, [%4];" \
                 : "=r"((r)[0]), "=r"((r)[1]), "=r"((r)[2]), "=r"((r)[3]) : "r"(addr))
#define MMA_BF16(d, a, b) \
    asm volatile("mma.sync.aligned.m16n8k16.row.col.f32.bf16.bf16.f32 " \
                 "{%0,%1,%2,%3}, {%4,%5,%6,%7}, {%8,%9}, {%0,%1,%2,%3};" \
                 : "+f"((d)[0]), "+f"((d)[1]), "+f"((d)[2]), "+f"((d)[3]) \
                 : "r"((a)[0]), "r"((a)[1]), "r"((a)[2]), "r"((a)[3]), \
                   "r"((b)[0]), "r"((b)[1]))

// =====================================================================
// bf16-split tensor-core GEMM. R13 structure with MKC=64: doubled
// K-depth per stage halves the per-chunk barrier/latency overhead.
// 512 threads (16 warps, 4x4, warp tile 32x32), CTA 128x128, K chunks
// of 64, double-buffered smem, register prefetch. A fp32 split hi/lo
// in-loop; B pre-split bf16 [Kp x ldb] zero-padded. blockIdx.z =
// batch. Inactive-N warps skip compute.
// =====================================================================
#define MBM 128
#define MBN 128
#define MKC 64
#define ASTR 72             // 64 + 8 pad (bf16 elems per A smem row)
#define BSTR 136            // 128 + 8 pad
#define OA_H 0
#define OA_L 18432          // 128*72*2
#define OB_H 36864
#define OB_L 54272          // OB_H + 64*136*2
#define BUFSZ 71680
#define MM_SMEM (2 * BUFSZ) // 143360

template<int DOMAX, int DORELU, int DORES>
__global__ __launch_bounds__(512, 1)
void mma_gemm(const float* __restrict__ A, int lda, long aStr,
              const bf16* __restrict__ Bh, const bf16* __restrict__ Bl,
              int ldb, long bStr,
              const float* __restrict__ bias, int biasStr,
              const float* __restrict__ R,
              float* __restrict__ C, int ldc, long cStr,
              int M, int K, int N)
{
    extern __shared__ char smem[];
    const uint32_t sb = smem_u32(smem);
    const int tid = threadIdx.x, lane = tid & 31, wid = tid >> 5;  // 16 warps
    const int wm = wid & 3, wn = wid >> 2;                          // 4 x 4
    const int m0 = blockIdx.y * MBM, n0 = blockIdx.x * MBN;
    const int z = blockIdx.z;
    A    += (size_t)z * aStr;
    Bh   += (size_t)z * bStr;
    Bl   += (size_t)z * bStr;
    bias += (size_t)z * biasStr;
    C    += (size_t)z * cStr;

    const int nch = (K + MKC - 1) / MKC;
    const bool wact = (n0 + wn * 32) < N;

    float acc[2][4][4];
#pragma unroll
    for (int i = 0; i < 2; i++)
#pragma unroll
        for (int j = 0; j < 4; j++)
#pragma unroll
            for (int k = 0; k < 4; k++) acc[i][j][k] = 0.f;

    float4 pa[4];
    uint4 pbh[2], pbl[2];
    const float4 z4 = make_float4(0.f, 0.f, 0.f, 0.f);
    const uint4 zu = make_uint4(0u, 0u, 0u, 0u);

    // A map: row = tid/4 (0..127), kbase = (tid%4)*16 (four float4s)
    const int ar = tid >> 2;
    const int akb = (tid & 3) * 16;
    // B map: k = tid/8 (0..63), col = (tid%8)*16 (two uint4s per h/l)
    const int bk = tid >> 3;
    const int bc = (tid & 7) * 16;

    auto load_regs = [&](int c) {
        const int k0 = c * MKC;
        const int gm = m0 + ar;
#pragma unroll
        for (int i = 0; i < 4; i++) {
            const int gk = k0 + akb + i * 4;
            pa[i] = (gm < M && gk < K) ? *(const float4*)(A + (size_t)gm * lda + gk) : z4;
        }
        const size_t brow = (size_t)(k0 + bk) * ldb;   // B rows zero-padded to Kp
#pragma unroll
        for (int g = 0; g < 2; g++) {
            const int gn = n0 + bc + g * 8;
            if (gn < ldb) {
                pbh[g] = *(const uint4*)(Bh + brow + gn);
                pbl[g] = *(const uint4*)(Bl + brow + gn);
            } else {
                pbh[g] = zu;
                pbl[g] = zu;
            }
        }
    };

    auto store_smem = [&](int buf) {
        const uint32_t bo = buf * BUFSZ;
        const uint32_t abase = bo + (uint32_t)(ar * ASTR + akb) * 2;
#pragma unroll
        for (int i = 0; i < 4; i++) {
            float4 v = pa[i];
            __nv_bfloat162 h01 = __float22bfloat162_rn(make_float2(v.x, v.y));
            __nv_bfloat162 h23 = __float22bfloat162_rn(make_float2(v.z, v.w));
            float2 f01 = __bfloat1622float2(h01);
            float2 f23 = __bfloat1622float2(h23);
            __nv_bfloat162 l01 = __float22bfloat162_rn(make_float2(v.x - f01.x, v.y - f01.y));
            __nv_bfloat162 l23 = __float22bfloat162_rn(make_float2(v.z - f23.x, v.w - f23.y));
            *(__nv_bfloat162*)(smem + OA_H + abase + i * 8)     = h01;
            *(__nv_bfloat162*)(smem + OA_H + abase + i * 8 + 4) = h23;
            *(__nv_bfloat162*)(smem + OA_L + abase + i * 8)     = l01;
            *(__nv_bfloat162*)(smem + OA_L + abase + i * 8 + 4) = l23;
        }
        const uint32_t bbase = bo + (uint32_t)(bk * BSTR + bc) * 2;
        *(uint4*)(smem + OB_H + bbase)      = pbh[0];
        *(uint4*)(smem + OB_H + bbase + 16) = pbh[1];
        *(uint4*)(smem + OB_L + bbase)      = pbl[0];
        *(uint4*)(smem + OB_L + bbase + 16) = pbl[1];
    };

    load_regs(0);
    store_smem(0);

    const int arow16 = lane & 15;
    const int hi8 = (lane >> 4) * 8;

    for (int c = 0; c < nch; c++) {
        __syncthreads();
        const int nxt = c + 1;
        if (nxt < nch) load_regs(nxt);

        if (wact) {
            const uint32_t bufo = (uint32_t)(c & 1) * BUFSZ;
            const uint32_t aH = sb + OA_H + bufo;
            const uint32_t aL = sb + OA_L + bufo;
            const uint32_t bH = sb + OB_H + bufo;
            const uint32_t bL = sb + OB_L + bufo;
#pragma unroll
            for (int ks = 0; ks < 4; ks++) {
                uint32_t ah[2][4], al[2][4];
#pragma unroll
                for (int mb = 0; mb < 2; mb++) {
                    const uint32_t ao =
                        (uint32_t)((wm * 32 + mb * 16 + arow16) * ASTR + ks * 16 + hi8) * 2;
                    LDSM_X4(ah[mb], aH + ao);
                    LDSM_X4(al[mb], aL + ao);
                }
                uint32_t bh[4][2], bl[4][2];
#pragma unroll
                for (int nb = 0; nb < 2; nb++) {
                    const uint32_t bo2 =
                        (uint32_t)((ks * 16 + arow16) * BSTR + wn * 32 + nb * 16 + hi8) * 2;
                    uint32_t r[4];
                    LDSM_X4T(r, bH + bo2);
                    bh[nb * 2][0] = r[0]; bh[nb * 2][1] = r[1];
                    bh[nb * 2 + 1][0] = r[2]; bh[nb * 2 + 1][1] = r[3];
                    LDSM_X4T(r, bL + bo2);
                    bl[nb * 2][0] = r[0]; bl[nb * 2][1] = r[1];
                    bl[nb * 2 + 1][0] = r[2]; bl[nb * 2 + 1][1] = r[3];
                }
#pragma unroll
                for (int mb = 0; mb < 2; mb++)
#pragma unroll
                    for (int f = 0; f < 4; f++) {
                        MMA_BF16(acc[mb][f], ah[mb], bh[f]);
                        MMA_BF16(acc[mb][f], al[mb], bh[f]);
                        MMA_BF16(acc[mb][f], ah[mb], bl[f]);
                    }
            }
        }

        if (nxt < nch) store_smem(nxt & 1);
    }

    if (!wact) return;

    // ---- epilogue ----
#pragma unroll
    for (int mb = 0; mb < 2; mb++) {
        const int rbase = m0 + wm * 32 + mb * 16;
#pragma unroll
        for (int f = 0; f < 4; f++) {
            const int cc = n0 + wn * 32 + f * 8 + (lane & 3) * 2;
            float d0 = acc[mb][f][0], d1 = acc[mb][f][1];
            float d2 = acc[mb][f][2], d3 = acc[mb][f][3];
            if (DOMAX) {
                const float b0v = (cc < N) ? bias[cc] : 0.f;
                const float b1v = (cc + 1 < N) ? bias[cc + 1] : 0.f;
                float v0 = fmaxf(d0 + b0v, 0.f), v1 = fmaxf(d1 + b1v, 0.f);
                float v2 = fmaxf(d2 + b0v, 0.f), v3 = fmaxf(d3 + b1v, 0.f);
#pragma unroll
                for (int off = 4; off < 32; off <<= 1) {
                    v0 = fmaxf(v0, __shfl_xor_sync(0xffffffffu, v0, off));
                    v1 = fmaxf(v1, __shfl_xor_sync(0xffffffffu, v1, off));
                    v2 = fmaxf(v2, __shfl_xor_sync(0xffffffffu, v2, off));
                    v3 = fmaxf(v3, __shfl_xor_sync(0xffffffffu, v3, off));
                }
                if ((lane >> 2) == 0 && cc < N) {
                    const int g0 = rbase >> 3, g1 = (rbase + 8) >> 3;
                    C[(size_t)g0 * ldc + cc] = v0;
                    C[(size_t)g1 * ldc + cc] = v2;
                    if (cc + 1 < N) {
                        C[(size_t)g0 * ldc + cc + 1] = v1;
                        C[(size_t)g1 * ldc + cc + 1] = v3;
                    }
                }
            } else {
                const int r = rbase + (lane >> 2);
                if (cc < N) {
                    const float b0v = bias[cc];
                    const float b1v = (cc + 1 < N) ? bias[cc + 1] : 0.f;
                    if (r < M) {
                        float x0 = d0 + b0v, x1 = d1 + b1v;
                        if (DORES) { x0 += R[(size_t)r * ldc + cc]; if (cc + 1 < N) x1 += R[(size_t)r * ldc + cc + 1]; }
                        if (DORELU) { x0 = fmaxf(x0, 0.f); x1 = fmaxf(x1, 0.f); }
                        C[(size_t)r * ldc + cc] = x0;
                        if (cc + 1 < N) C[(size_t)r * ldc + cc + 1] = x1;
                    }
                    if (r + 8 < M) {
                        float x2 = d2 + b0v, x3 = d3 + b1v;
                        if (DORES) { x2 += R[(size_t)(r + 8) * ldc + cc]; if (cc + 1 < N) x3 += R[(size_t)(r + 8) * ldc + cc + 1]; }
                        if (DORELU) { x2 = fmaxf(x2, 0.f); x3 = fmaxf(x3, 0.f); }
                        C[(size_t)(r + 8) * ldc + cc] = x2;
                        if (cc + 1 < N) C[(size_t)(r + 8) * ldc + cc + 1] = x3;
                    }
                }
            }
        }
    }
}

// ---------------- batched weight split (with optional appended src2) ----------------
#define NJOBS 18
struct SJobs {
    const float* src[NJOBS];
    const float* src2[NJOBS];
    bf16* dh[NJOBS];
    bf16* dl[NJOBS];
    int K[NJOBS], N[NJOBS], N2[NJOBS], Kp[NJOBS], Np[NJOBS];
};

__global__ void split_jobs_kernel(SJobs js)
{
    const int job = blockIdx.y;
    const int Np = js.Np[job], K = js.K[job], N = js.N[job], N2 = js.N2[job];
    const int total = js.Kp[job] * Np;
    const float* src = js.src[job];
    const float* src2 = js.src2[job];
    bf16* dh = js.dh[job];
    bf16* dl = js.dl[job];
    for (int idx = blockIdx.x * blockDim.x + threadIdx.x; idx < total;
         idx += gridDim.x * blockDim.x) {
        const int k = idx / Np, n = idx - k * Np;
        float v = 0.f;
        if (k < K) {
            if (n < N) v = src[k * N + n];
            else if (n < N + N2) v = src2[k * N2 + (n - N)];
        }
        bf16 h, l; split2(v, h, l);
        dh[idx] = h;
        dl[idx] = l;
    }
}

// combined bias [bf | bh] per iteration
__global__ void fill_cbias_kernel(const float* __restrict__ bf_, const float* __restrict__ bh_,
                                  float* __restrict__ cb)
{
    int idx = blockIdx.x * blockDim.x + threadIdx.x;
    if (idx >= TIT * NU) return;
    int t = idx / NU, n = idx - t * NU;
    cb[idx] = (n < SD) ? bf_[t * SD + n] : bh_[t * 3 + (n - SD)];
}

// ---------------- small-N generic GEMM (N=4, N=7 heads), z-batched ----------------
#define BM 64
#define BN 64
#define BK 16
__global__ void sgemm_bias(const float* __restrict__ A, int lda, long aStr,
                           const float* __restrict__ B, long bStr,
                           const float* __restrict__ bias, int biasStr,
                           float* __restrict__ C, long cStr,
                           int M, int K, int N, int ldc, int doRelu)
{
    __shared__ float As[BK][BM + 1];
    __shared__ float Bs[BK][BN];
    int tid = threadIdx.x;
    int tx = tid & 15, ty = tid >> 4;
    int m0 = blockIdx.y * BM, n0 = blockIdx.x * BN;
    const int z = blockIdx.z;
    A    += (size_t)z * aStr;
    B    += (size_t)z * bStr;
    bias += (size_t)z * biasStr;
    C    += (size_t)z * cStr;
    float acc[4][4] = {};

    for (int k0 = 0; k0 < K; k0 += BK) {
        {
            int m  = tid >> 2;
            int kb = (tid & 3) * 4;
            int gm = m0 + m;
#pragma unroll
            for (int i = 0; i < 4; i++) {
                int kk = kb + i, gk = k0 + kk;
                As[kk][m] = (gm < M && gk < K) ? A[(size_t)gm * lda + gk] : 0.f;
            }
        }
        {
            int kk = tid >> 4;
            int nb = (tid & 15) * 4;
            int gk = k0 + kk;
#pragma unroll
            for (int i = 0; i < 4; i++) {
                int n = nb + i, gn = n0 + n;
                Bs[kk][n] = (gk < K && gn < N) ? B[(size_t)gk * N + gn] : 0.f;
            }
        }
        __syncthreads();
#pragma unroll
        for (int kk = 0; kk < BK; kk++) {
            float a[4], b[4];
#pragma unroll
            for (int i = 0; i < 4; i++) a[i] = As[kk][ty * 4 + i];
#pragma unroll
            for (int j = 0; j < 4; j++) b[j] = Bs[kk][tx * 4 + j];
#pragma unroll
            for (int i = 0; i < 4; i++)
#pragma unroll
                for (int j = 0; j < 4; j++)
                    acc[i][j] += a[i] * b[j];
        }
        __syncthreads();
    }
#pragma unroll
    for (int i = 0; i < 4; i++) {
        int gm = m0 + ty * 4 + i;
        if (gm >= M) continue;
#pragma unroll
        for (int j = 0; j < 4; j++) {
            int gn = n0 + tx * 4 + j;
            if (gn >= N) continue;
            float v = acc[i][j] + bias[gn];
            if (doRelu) v = fmaxf(v, 0.f);
            C[(size_t)gm * ldc + gn] = v;
        }
    }
}

// ---------------- init MLP layer0 ----------------
__global__ void layer0_kernel(const float* __restrict__ kp, const float* __restrict__ W,
                              const float* __restrict__ b, float* __restrict__ out)
{
    int idx = blockIdx.x * blockDim.x + threadIdx.x;
    if (idx >= MKP * 64) return;
    int row = idx >> 6, j = idx & 63;
    const float* x = kp + row * KPD;
    float v = b[j];
#pragma unroll
    for (int i = 0; i < KPD; i++) v += x[i] * W[i * 64 + j];
    out[idx] = fmaxf(v, 0.f);
}

// ---------------- CSR construction ----------------
__global__ void zero_counts_kernel()
{
    int i = blockIdx.x * blockDim.x + threadIdx.x;
    if (i <= NV) g_counts[i] = 0;
}
__global__ void hist_kernel(const int* __restrict__ ei)
{
    int e = blockIdx.x * blockDim.x + threadIdx.x;
    if (e >= NE) return;
    atomicAdd(&g_counts[ei[NE + e]], 1);
}
__global__ void scan_kernel()
{
    __shared__ int sh[1024];
    int t = threadIdx.x;
    const int chunk = (NV + 1023) / 1024;
    int lo = t * chunk, hi = min(NV, lo + chunk);
    int sum = 0;
    for (int i = lo; i < hi; i++) sum += g_counts[i];
    sh[t] = sum;
    __syncthreads();
    for (int off = 1; off < 1024; off <<= 1) {
        int v = (t >= off) ? sh[t - off] : 0;
        __syncthreads();
        sh[t] += v;
        __syncthreads();
    }
    int run = (t == 0) ? 0 : sh[t - 1];
    for (int i = lo; i < hi; i++) {
        g_offs[i] = run;
        g_cursor[i] = run;
        run += g_counts[i];
    }
    if (t == 1023) g_offs[NV] = sh[1023];
}
__global__ void scatter_kernel(const int* __restrict__ ei)
{
    int e = blockIdx.x * blockDim.x + threadIdx.x;
    if (e >= NE) return;
    int dst = ei[NE + e];
    int slot = atomicAdd(&g_cursor[dst], 1);
    g_sortedSrc[slot] = ei[e];
}

// ---------------- fused edge message + segment max ----------------
// u layout: [NV x USTR]; cols 0..299 = s@Wf'+bf, cols 300..302 = dx
#define ECHUNK 64
__global__ void edge_aggr_kernel(const float* __restrict__ u, const float* __restrict__ pos,
                                 const float* __restrict__ Wf3,
                                 float* __restrict__ aggr)
{
    __shared__ float wsh[3 * SD];
    __shared__ float dsh[ECHUNK * 3];
    __shared__ int   ssh[ECHUNK];
    int v = blockIdx.x;
    int t = threadIdx.x;   // 320
    for (int i = t; i < 3 * SD; i += blockDim.x) wsh[i] = Wf3[i];

    float pvx = pos[v * 3 + 0], pvy = pos[v * 3 + 1], pvz = pos[v * 3 + 2];
    float dvx = u[(size_t)v * USTR + 300];
    float dvy = u[(size_t)v * USTR + 301];
    float dvz = u[(size_t)v * USTR + 302];
    int lo = g_offs[v], hi = g_offs[v + 1];
    float best = 0.f;
    __syncthreads();

    for (int c0 = lo; c0 < hi; c0 += ECHUNK) {
        int cnt = min(ECHUNK, hi - c0);
        if (t < cnt) {
            int src = g_sortedSrc[c0 + t];
            ssh[t] = src;
            dsh[t * 3 + 0] = pos[src * 3 + 0] - pvx + dvx;
            dsh[t * 3 + 1] = pos[src * 3 + 1] - pvy + dvy;
            dsh[t * 3 + 2] = pos[src * 3 + 2] - pvz + dvz;
        }
        __syncthreads();
        if (t < SD) {
            float w0 = wsh[t], w1 = wsh[SD + t], w2 = wsh[2 * SD + t];
            for (int j = 0; j < cnt; j++) {
                float c = dsh[j * 3 + 0] * w0 + dsh[j * 3 + 1] * w1 + dsh[j * 3 + 2] * w2;
                float val = u[(size_t)ssh[j] * USTR + t] + c;
                best = fmaxf(best, val);
            }
        }
        __syncthreads();
    }
    if (t < SD) aggr[v * SD + t] = best;
}

// ---------------- host launch ----------------
static inline dim3 mm_grid(int M, int N, int z = 1)
{
    return dim3((N + MBN - 1) / MBN, (M + MBM - 1) / MBM, z);
}

template<typename T>
static T* sym(const void* s) { void* p; cudaGetSymbolAddress(&p, s); return (T*)p; }

extern "C" void kernel_launch(void* const* d_in, const int* in_sizes, int n_in,
                              void* d_out, int out_size)
{
    const float* key_points = (const float*)d_in[0];
    const float* pos        = (const float*)d_in[1];
    const int*   edge_index = (const int*)d_in[3];
    const float* Wi0 = (const float*)d_in[4];   const float* bi0 = (const float*)d_in[5];
    const float* Wi1 = (const float*)d_in[6];   const float* bi1 = (const float*)d_in[7];
    const float* Wi2 = (const float*)d_in[8];   const float* bi2 = (const float*)d_in[9];
    const float* Wa  = (const float*)d_in[10];  const float* ba  = (const float*)d_in[11];
    const float* Wh  = (const float*)d_in[12];  const float* bh  = (const float*)d_in[13];
    const float* Wf  = (const float*)d_in[14];  const float* bf  = (const float*)d_in[15];
    const float* Wg  = (const float*)d_in[16];  const float* bg  = (const float*)d_in[17];
    const float* Wc1 = (const float*)d_in[18];  const float* bc1 = (const float*)d_in[19];
    const float* Wc2 = (const float*)d_in[20];  const float* bc2 = (const float*)d_in[21];
    const float* Wl1 = (const float*)d_in[22];  const float* bl1 = (const float*)d_in[23];
    const float* Wl2 = (const float*)d_in[24];  const float* bl2 = (const float*)d_in[25];
    const float* Wl3 = (const float*)d_in[26];  const float* bl3 = (const float*)d_in[27];

    float* out_cls = (float*)d_out;
    float* out_reg = (float*)d_out + NV * NC;

    float *h0 = sym<float>(g_h0), *h1 = sym<float>(g_h1), *kpmax = sym<float>(g_kpmax);
    float *sA = sym<float>(g_sA), *sB = sym<float>(g_sB), *u = sym<float>(g_u);
    float *aggr = sym<float>(g_aggr), *cbias = sym<float>(g_cbias);
    float *c1 = sym<float>(g_c1), *l1all = sym<float>(g_l1all), *l2all = sym<float>(g_l2all);
    bf16 *wi1h = sym<bf16>(g_wi1h), *wi1l = sym<bf16>(g_wi1l);
    bf16 *wi2h = sym<bf16>(g_wi2h), *wi2l = sym<bf16>(g_wi2l);
    bf16 *wah = sym<bf16>(g_wah),   *wal = sym<bf16>(g_wal);
    bf16 *wfph = sym<bf16>(g_wfph), *wfpl = sym<bf16>(g_wfpl);
    bf16 *wgh = sym<bf16>(g_wgh),   *wgl = sym<bf16>(g_wgl);
    bf16 *wc1h = sym<bf16>(g_wc1h), *wc1l = sym<bf16>(g_wc1l);
    bf16 *wl1h = sym<bf16>(g_wl1h), *wl1l = sym<bf16>(g_wl1l);
    bf16 *wl2h = sym<bf16>(g_wl2h), *wl2l = sym<bf16>(g_wl2l);

    cudaFuncSetAttribute(mma_gemm<0,1,0>, cudaFuncAttributeMaxDynamicSharedMemorySize, MM_SMEM);
    cudaFuncSetAttribute(mma_gemm<1,0,0>, cudaFuncAttributeMaxDynamicSharedMemorySize, MM_SMEM);
    cudaFuncSetAttribute(mma_gemm<0,0,0>, cudaFuncAttributeMaxDynamicSharedMemorySize, MM_SMEM);
    cudaFuncSetAttribute(mma_gemm<0,0,1>, cudaFuncAttributeMaxDynamicSharedMemorySize, MM_SMEM);

    // ---- launch 0: weight splits (Wf jobs get Wh appended as cols 300..302) ----
    {
        SJobs js;
        int j = 0;
        auto add = [&](const float* src, const float* src2, int N2,
                       bf16* dh, bf16* dl, int K, int N, int Kp, int Np) {
            js.src[j] = src; js.src2[j] = src2; js.N2[j] = N2;
            js.dh[j] = dh; js.dl[j] = dl;
            js.K[j] = K; js.N[j] = N; js.Kp[j] = Kp; js.Np[j] = Np; j++;
        };
        add(Wi1, nullptr, 0, wi1h, wi1l, 64, 128, 64, 128);
        add(Wi2, nullptr, 0, wi2h, wi2l, 128, SD, 128, NP3);
        add(Wa,  nullptr, 0, wah,  wal,  SD, SD, SDP, NP3);
        for (int t = 0; t < TIT; t++)
            add(Wf + t * (SD + 3) * SD + 3 * SD, Wh + t * SD * 3, 3,
                wfph + t * SDP * NP3, wfpl + t * SDP * NP3, SD, SD, SDP, NP3);
        for (int t = 0; t < TIT; t++)
            add(Wg + t * SD * SD, nullptr, 0, wgh + t * SDP * NP3, wgl + t * SDP * NP3,
                SD, SD, SDP, NP3);
        add(Wc1, nullptr, 0, wc1h, wc1l, SD, 64, SDP, 64);
        for (int c = 0; c < NC; c++)
            add(Wl1 + c * SD * 64, nullptr, 0, wl1h + c * SDP * 64, wl1l + c * SDP * 64,
                SD, 64, SDP, 64);
        for (int c = 0; c < NC; c++)
            add(Wl2 + c * 64 * 64, nullptr, 0, wl2h + c * 64 * 64, wl2l + c * 64 * 64,
                64, 64, 64, 64);
        split_jobs_kernel<<<dim3(64, NJOBS), 256>>>(js);
    }

    // launches 1-2 (so profiled launch index 3 is the kpmax DOMAX GEMM)
    layer0_kernel<<<(MKP * 64 + 255) / 256, 256>>>(key_points, Wi0, bi0, h0);
    mma_gemm<0,1,0><<<mm_grid(MKP, 128), 512, MM_SMEM>>>(
        h0, 64, 0, wi1h, wi1l, 128, 0, bi1, 0, nullptr, h1, 128, 0, MKP, 64, 128);

    // ---- launch 3: kpmax fused GEMM+segment-max (ncu capture target) ----
    mma_gemm<1,0,0><<<mm_grid(MKP, SD), 512, MM_SMEM>>>(
        h1, 128, 0, wi2h, wi2l, NP3, 0, bi2, 0, nullptr, kpmax, SD, 0, MKP, 128, SD);
    mma_gemm<0,1,0><<<mm_grid(NV, SD), 512, MM_SMEM>>>(
        kpmax, SD, 0, wah, wal, NP3, 0, ba, 0, nullptr, sA, SD, 0, NV, SD, SD);

    // ---- combined bias + CSR build ----
    fill_cbias_kernel<<<(TIT * NU + 255) / 256, 256>>>(bf, bh, cbias);
    zero_counts_kernel<<<(NV + 256) / 256, 256>>>();
    hist_kernel<<<(NE + 255) / 256, 256>>>(edge_index);
    scan_kernel<<<1, 1024>>>();
    scatter_kernel<<<(NE + 255) / 256, 256>>>(edge_index);

    // ---- GNN iterations (dx fused into u GEMM as cols 300..302) ----
    float* s_cur = sA;
    float* s_nxt = sB;
    for (int t = 0; t < TIT; t++) {
        const float* Wft = Wf + t * (SD + 3) * SD;   // rows 0..2 for edge_aggr
        const float* bgt = bg + t * SD;

        // u' = s @ [Wf' | Wh] + [bf | bh]   (N = 303, row stride 320)
        mma_gemm<0,0,0><<<mm_grid(NV, NU), 512, MM_SMEM>>>(
            s_cur, SD, 0, wfph + t * SDP * NP3, wfpl + t * SDP * NP3, NP3, 0,
            cbias + t * NU, 0, nullptr, u, USTR, 0, NV, SD, NU);
        edge_aggr_kernel<<<NV, 320>>>(u, pos, Wft, aggr);
        mma_gemm<0,0,1><<<mm_grid(NV, SD), 512, MM_SMEM>>>(
            aggr, SD, 0, wgh + t * SDP * NP3, wgl + t * SDP * NP3, NP3, 0,
            bgt, 0, s_cur, s_nxt, SD, 0, NV, SD, SD);
        float* tmp = s_cur; s_cur = s_nxt; s_nxt = tmp;
    }

    // ---- heads (z-batched) ----
    mma_gemm<0,1,0><<<mm_grid(NV, 64), 512, MM_SMEM>>>(
        s_cur, SD, 0, wc1h, wc1l, 64, 0, bc1, 0, nullptr, c1, 64, 0, NV, SD, 64);
    sgemm_bias<<<dim3(1, (NV + BM - 1) / BM, 1), 256>>>(
        c1, 64, 0, Wc2, 0, bc2, 0, out_cls, 0, NV, 64, NC, NC, 1);
    mma_gemm<0,1,0><<<mm_grid(NV, 64, NC), 512, MM_SMEM>>>(
        s_cur, SD, 0, wl1h, wl1l, 64, (long)SDP * 64, bl1, 64,
        nullptr, l1all, 256, 64, NV, SD, 64);
    mma_gemm<0,1,0><<<mm_grid(NV, 64, NC), 512, MM_SMEM>>>(
        l1all, 256, 64, wl2h, wl2l, 64, (long)64 * 64, bl2, 64,
        nullptr, l2all, 256, 64, NV, 64, 64);
    sgemm_bias<<<dim3(1, (NV + BM - 1) / BM, NC), 256>>>(
        l2all, 256, 64, Wl3, (long)64 * 7, bl3, 7, out_reg, 7, NV, 64, 7, NC * 7, 1);
}

// round 15
// speedup vs baseline: 1.0256x; 1.0256x over previous
#include <cuda_runtime.h>
#include <cuda_bf16.h>
#include <cstdint>

// ---------------- problem constants ----------------
#define NV   20000
#define KPV  8
#define MKP  (NV * KPV)
#define NE   320000
#define KPD  4
#define SD   300
#define SDP  320            // K=300 padded to 32-mult
#define NP3  384            // N padded for B (3 x 128 tiles)
#define NU   303            // u GEMM N: 300 (Wf') + 3 (Wh)
#define USTR 320            // u row stride
#define TIT  3
#define NC   4
#define NH   5              // head batch: c1 + 4 classes
#define L1STR 320           // l1all row stride (5 x 64)

typedef __nv_bfloat16 bf16;

// ---------------- scratch ----------------
__device__ float g_h0[MKP * 64];
__device__ float g_h1[MKP * 128];
__device__ float g_kpmax[NV * SD];
__device__ float g_sA[NV * SD];
__device__ float g_sB[NV * SD];
__device__ float g_u[NV * USTR];        // cols 0..299 = u, 300..302 = dx
__device__ float g_aggr[NV * SD];
__device__ float g_l1all[NV * L1STR];   // cols 0..63 = c1, 64.. = l1 per class
__device__ float g_l2all[NV * 256];
__device__ float g_cbias[TIT * NU];     // [bf | bh] per iteration
__device__ float g_hbias[NH * 64];      // [bc1 | bl1(4x64)]
// weight splits (bf16 hi/lo), K padded to 32-mult
__device__ bf16 g_wi1h[64 * 128],        g_wi1l[64 * 128];
__device__ bf16 g_wi2h[128 * NP3],       g_wi2l[128 * NP3];
__device__ bf16 g_wah[SDP * NP3],        g_wal[SDP * NP3];
__device__ bf16 g_wfph[TIT * SDP * NP3], g_wfpl[TIT * SDP * NP3];  // [Wf' | Wh]
__device__ bf16 g_wgh[TIT * SDP * NP3],  g_wgl[TIT * SDP * NP3];
__device__ bf16 g_whh[NH * SDP * 64],    g_whl[NH * SDP * 64];     // [Wc1 | Wl1 x4]
__device__ bf16 g_wl2h[NC * 64 * 64],    g_wl2l[NC * 64 * 64];
// CSR
__device__ int g_counts[NV + 1];
__device__ int g_offs[NV + 1];
__device__ int g_cursor[NV];
__device__ int g_sortedSrc[NE];

// ---------------- helpers ----------------
__device__ __forceinline__ uint32_t smem_u32(const void* p) {
    uint32_t a;
    asm("{ .reg .u64 t; cvta.to.shared.u64 t, %1; cvt.u32.u64 %0, t; }" : "=r"(a) : "l"(p));
    return a;
}
__device__ __forceinline__ void split2(float x, bf16& h, bf16& l) {
    h = __float2bfloat16(x);
    l = __float2bfloat16(x - __bfloat162float(h));
}

#define LDSM_X4(r, addr) \
    asm volatile("ldmatrix.sync.aligned.m8n8.x4.shared.b16 {%0,%1,%2,%3}, [%4];" \
                 : "=r"((r)[0]), "=r"((r)[1]), "=r"((r)[2]), "=r"((r)[3]) : "r"(addr))
#define LDSM_X4T(r, addr) \
    asm volatile("ldmatrix.sync.aligned.m8n8.x4.trans.shared.b16 {%0,%1,%2,%3}, [%4];" \
                 : "=r"((r)[0]), "=r"((r)[1]), "=r"((r)[2]), "=r"((r)[3]) : "r"(addr))
#define MMA_BF16(d, a, b) \
    asm volatile("mma.sync.aligned.m16n8k16.row.col.f32.bf16.bf16.f32 " \
                 "{%0,%1,%2,%3}, {%4,%5,%6,%7}, {%8,%9}, {%0,%1,%2,%3};" \
                 : "+f"((d)[0]), "+f"((d)[1]), "+f"((d)[2]), "+f"((d)[3]) \
                 : "r"((a)[0]), "r"((a)[1]), "r"((a)[2]), "r"((a)[3]), \
                   "r"((b)[0]), "r"((b)[1]))

// =====================================================================
// bf16-split tensor-core GEMM (R13 core, MKC=32 — best measured).
// 512 threads (16 warps, 4x4, warp tile 32x32), CTA 128x128, K chunks
// of 32, double-buffered smem, register prefetch. A fp32 split hi/lo
// in-loop; B pre-split bf16 [Kp x ldb] zero-padded. blockIdx.z =
// batch. Inactive-N warps skip compute.
// =====================================================================
#define MBM 128
#define MBN 128
#define MKC 32
#define ASTR 40
#define BSTR 136
#define OA_H 0
#define OA_L 10240
#define OB_H 20480
#define OB_L 29184
#define BUFSZ 37888
#define MM_SMEM (2 * BUFSZ)

template<int DOMAX, int DORELU, int DORES>
__global__ __launch_bounds__(512, 1)
void mma_gemm(const float* __restrict__ A, int lda, long aStr,
              const bf16* __restrict__ Bh, const bf16* __restrict__ Bl,
              int ldb, long bStr,
              const float* __restrict__ bias, int biasStr,
              const float* __restrict__ R,
              float* __restrict__ C, int ldc, long cStr,
              int M, int K, int N)
{
    extern __shared__ char smem[];
    const uint32_t sb = smem_u32(smem);
    const int tid = threadIdx.x, lane = tid & 31, wid = tid >> 5;  // 16 warps
    const int wm = wid & 3, wn = wid >> 2;                          // 4 x 4
    const int m0 = blockIdx.y * MBM, n0 = blockIdx.x * MBN;
    const int z = blockIdx.z;
    A    += (size_t)z * aStr;
    Bh   += (size_t)z * bStr;
    Bl   += (size_t)z * bStr;
    bias += (size_t)z * biasStr;
    C    += (size_t)z * cStr;

    const int nch = (K + MKC - 1) / MKC;
    const bool wact = (n0 + wn * 32) < N;

    float acc[2][4][4];
#pragma unroll
    for (int i = 0; i < 2; i++)
#pragma unroll
        for (int j = 0; j < 4; j++)
#pragma unroll
            for (int k = 0; k < 4; k++) acc[i][j][k] = 0.f;

    float4 pa[2];
    uint4 pbh, pbl;
    const float4 z4 = make_float4(0.f, 0.f, 0.f, 0.f);
    const uint4 zu = make_uint4(0u, 0u, 0u, 0u);

    const int ar = tid >> 2;
    const int akb = (tid & 3) * 8;
    const int bk = tid >> 4;
    const int bc = (tid & 15) * 8;

    auto load_regs = [&](int c) {
        const int k0 = c * MKC;
        const int gm = m0 + ar;
#pragma unroll
        for (int i = 0; i < 2; i++) {
            const int gk = k0 + akb + i * 4;
            pa[i] = (gm < M && gk < K) ? *(const float4*)(A + (size_t)gm * lda + gk) : z4;
        }
        const int gn = n0 + bc;
        const size_t brow = (size_t)(k0 + bk) * ldb;
        if (gn < ldb) {
            pbh = *(const uint4*)(Bh + brow + gn);
            pbl = *(const uint4*)(Bl + brow + gn);
        } else {
            pbh = zu;
            pbl = zu;
        }
    };

    auto store_smem = [&](int buf) {
        const uint32_t bo = buf * BUFSZ;
        const uint32_t abase = bo + (uint32_t)(ar * ASTR + akb) * 2;
#pragma unroll
        for (int i = 0; i < 2; i++) {
            float4 v = pa[i];
            __nv_bfloat162 h01 = __float22bfloat162_rn(make_float2(v.x, v.y));
            __nv_bfloat162 h23 = __float22bfloat162_rn(make_float2(v.z, v.w));
            float2 f01 = __bfloat1622float2(h01);
            float2 f23 = __bfloat1622float2(h23);
            __nv_bfloat162 l01 = __float22bfloat162_rn(make_float2(v.x - f01.x, v.y - f01.y));
            __nv_bfloat162 l23 = __float22bfloat162_rn(make_float2(v.z - f23.x, v.w - f23.y));
            *(__nv_bfloat162*)(smem + OA_H + abase + i * 8)     = h01;
            *(__nv_bfloat162*)(smem + OA_H + abase + i * 8 + 4) = h23;
            *(__nv_bfloat162*)(smem + OA_L + abase + i * 8)     = l01;
            *(__nv_bfloat162*)(smem + OA_L + abase + i * 8 + 4) = l23;
        }
        const uint32_t boff = bo + (uint32_t)(bk * BSTR + bc) * 2;
        *(uint4*)(smem + OB_H + boff) = pbh;
        *(uint4*)(smem + OB_L + boff) = pbl;
    };

    load_regs(0);
    store_smem(0);

    const int arow16 = lane & 15;
    const int hi8 = (lane >> 4) * 8;

    for (int c = 0; c < nch; c++) {
        __syncthreads();
        const int nxt = c + 1;
        if (nxt < nch) load_regs(nxt);

        if (wact) {
            const uint32_t bufo = (uint32_t)(c & 1) * BUFSZ;
            const uint32_t aH = sb + OA_H + bufo;
            const uint32_t aL = sb + OA_L + bufo;
            const uint32_t bH = sb + OB_H + bufo;
            const uint32_t bL = sb + OB_L + bufo;
#pragma unroll
            for (int ks = 0; ks < 2; ks++) {
                uint32_t ah[2][4], al[2][4];
#pragma unroll
                for (int mb = 0; mb < 2; mb++) {
                    const uint32_t ao =
                        (uint32_t)((wm * 32 + mb * 16 + arow16) * ASTR + ks * 16 + hi8) * 2;
                    LDSM_X4(ah[mb], aH + ao);
                    LDSM_X4(al[mb], aL + ao);
                }
                uint32_t bh[4][2], bl[4][2];
#pragma unroll
                for (int nb = 0; nb < 2; nb++) {
                    const uint32_t bo2 =
                        (uint32_t)((ks * 16 + arow16) * BSTR + wn * 32 + nb * 16 + hi8) * 2;
                    uint32_t r[4];
                    LDSM_X4T(r, bH + bo2);
                    bh[nb * 2][0] = r[0]; bh[nb * 2][1] = r[1];
                    bh[nb * 2 + 1][0] = r[2]; bh[nb * 2 + 1][1] = r[3];
                    LDSM_X4T(r, bL + bo2);
                    bl[nb * 2][0] = r[0]; bl[nb * 2][1] = r[1];
                    bl[nb * 2 + 1][0] = r[2]; bl[nb * 2 + 1][1] = r[3];
                }
#pragma unroll
                for (int mb = 0; mb < 2; mb++)
#pragma unroll
                    for (int f = 0; f < 4; f++) {
                        MMA_BF16(acc[mb][f], ah[mb], bh[f]);
                        MMA_BF16(acc[mb][f], al[mb], bh[f]);
                        MMA_BF16(acc[mb][f], ah[mb], bl[f]);
                    }
            }
        }

        if (nxt < nch) store_smem(nxt & 1);
    }

    if (!wact) return;

    // ---- epilogue ----
#pragma unroll
    for (int mb = 0; mb < 2; mb++) {
        const int rbase = m0 + wm * 32 + mb * 16;
#pragma unroll
        for (int f = 0; f < 4; f++) {
            const int cc = n0 + wn * 32 + f * 8 + (lane & 3) * 2;
            float d0 = acc[mb][f][0], d1 = acc[mb][f][1];
            float d2 = acc[mb][f][2], d3 = acc[mb][f][3];
            if (DOMAX) {
                const float b0v = (cc < N) ? bias[cc] : 0.f;
                const float b1v = (cc + 1 < N) ? bias[cc + 1] : 0.f;
                float v0 = fmaxf(d0 + b0v, 0.f), v1 = fmaxf(d1 + b1v, 0.f);
                float v2 = fmaxf(d2 + b0v, 0.f), v3 = fmaxf(d3 + b1v, 0.f);
#pragma unroll
                for (int off = 4; off < 32; off <<= 1) {
                    v0 = fmaxf(v0, __shfl_xor_sync(0xffffffffu, v0, off));
                    v1 = fmaxf(v1, __shfl_xor_sync(0xffffffffu, v1, off));
                    v2 = fmaxf(v2, __shfl_xor_sync(0xffffffffu, v2, off));
                    v3 = fmaxf(v3, __shfl_xor_sync(0xffffffffu, v3, off));
                }
                if ((lane >> 2) == 0 && cc < N) {
                    const int g0 = rbase >> 3, g1 = (rbase + 8) >> 3;
                    C[(size_t)g0 * ldc + cc] = v0;
                    C[(size_t)g1 * ldc + cc] = v2;
                    if (cc + 1 < N) {
                        C[(size_t)g0 * ldc + cc + 1] = v1;
                        C[(size_t)g1 * ldc + cc + 1] = v3;
                    }
                }
            } else {
                const int r = rbase + (lane >> 2);
                if (cc < N) {
                    const float b0v = bias[cc];
                    const float b1v = (cc + 1 < N) ? bias[cc + 1] : 0.f;
                    if (r < M) {
                        float x0 = d0 + b0v, x1 = d1 + b1v;
                        if (DORES) { x0 += R[(size_t)r * ldc + cc]; if (cc + 1 < N) x1 += R[(size_t)r * ldc + cc + 1]; }
                        if (DORELU) { x0 = fmaxf(x0, 0.f); x1 = fmaxf(x1, 0.f); }
                        C[(size_t)r * ldc + cc] = x0;
                        if (cc + 1 < N) C[(size_t)r * ldc + cc + 1] = x1;
                    }
                    if (r + 8 < M) {
                        float x2 = d2 + b0v, x3 = d3 + b1v;
                        if (DORES) { x2 += R[(size_t)(r + 8) * ldc + cc]; if (cc + 1 < N) x3 += R[(size_t)(r + 8) * ldc + cc + 1]; }
                        if (DORELU) { x2 = fmaxf(x2, 0.f); x3 = fmaxf(x3, 0.f); }
                        C[(size_t)(r + 8) * ldc + cc] = x2;
                        if (cc + 1 < N) C[(size_t)(r + 8) * ldc + cc + 1] = x3;
                    }
                }
            }
        }
    }
}

// ---------------- batched weight split (with optional appended src2) ----------------
#define NJOBS 18
struct SJobs {
    const float* src[NJOBS];
    const float* src2[NJOBS];
    bf16* dh[NJOBS];
    bf16* dl[NJOBS];
    int K[NJOBS], N[NJOBS], N2[NJOBS], Kp[NJOBS], Np[NJOBS];
};

__global__ void split_jobs_kernel(SJobs js)
{
    const int job = blockIdx.y;
    const int Np = js.Np[job], K = js.K[job], N = js.N[job], N2 = js.N2[job];
    const int total = js.Kp[job] * Np;
    const float* src = js.src[job];
    const float* src2 = js.src2[job];
    bf16* dh = js.dh[job];
    bf16* dl = js.dl[job];
    for (int idx = blockIdx.x * blockDim.x + threadIdx.x; idx < total;
         idx += gridDim.x * blockDim.x) {
        const int k = idx / Np, n = idx - k * Np;
        float v = 0.f;
        if (k < K) {
            if (n < N) v = src[k * N + n];
            else if (n < N + N2) v = src2[k * N2 + (n - N)];
        }
        bf16 h, l; split2(v, h, l);
        dh[idx] = h;
        dl[idx] = l;
    }
}

// combined biases: [bf | bh] per iteration, and [bc1 | bl1 x4]
__global__ void fill_bias_kernel(const float* __restrict__ bf_, const float* __restrict__ bh_,
                                 const float* __restrict__ bc1_, const float* __restrict__ bl1_,
                                 float* __restrict__ cb, float* __restrict__ hb)
{
    int idx = blockIdx.x * blockDim.x + threadIdx.x;
    if (idx < TIT * NU) {
        int t = idx / NU, n = idx - t * NU;
        cb[idx] = (n < SD) ? bf_[t * SD + n] : bh_[t * 3 + (n - SD)];
    }
    if (idx < NH * 64) {
        hb[idx] = (idx < 64) ? bc1_[idx] : bl1_[idx - 64];
    }
}

// ---------------- small-N generic GEMM (N=4, N=7 heads), z-batched ----------------
#define BM 64
#define BN 64
#define BK 16
__global__ void sgemm_bias(const float* __restrict__ A, int lda, long aStr,
                           const float* __restrict__ B, long bStr,
                           const float* __restrict__ bias, int biasStr,
                           float* __restrict__ C, long cStr,
                           int M, int K, int N, int ldc, int doRelu)
{
    __shared__ float As[BK][BM + 1];
    __shared__ float Bs[BK][BN];
    int tid = threadIdx.x;
    int tx = tid & 15, ty = tid >> 4;
    int m0 = blockIdx.y * BM, n0 = blockIdx.x * BN;
    const int z = blockIdx.z;
    A    += (size_t)z * aStr;
    B    += (size_t)z * bStr;
    bias += (size_t)z * biasStr;
    C    += (size_t)z * cStr;
    float acc[4][4] = {};

    for (int k0 = 0; k0 < K; k0 += BK) {
        {
            int m  = tid >> 2;
            int kb = (tid & 3) * 4;
            int gm = m0 + m;
#pragma unroll
            for (int i = 0; i < 4; i++) {
                int kk = kb + i, gk = k0 + kk;
                As[kk][m] = (gm < M && gk < K) ? A[(size_t)gm * lda + gk] : 0.f;
            }
        }
        {
            int kk = tid >> 4;
            int nb = (tid & 15) * 4;
            int gk = k0 + kk;
#pragma unroll
            for (int i = 0; i < 4; i++) {
                int n = nb + i, gn = n0 + n;
                Bs[kk][n] = (gk < K && gn < N) ? B[(size_t)gk * N + gn] : 0.f;
            }
        }
        __syncthreads();
#pragma unroll
        for (int kk = 0; kk < BK; kk++) {
            float a[4], b[4];
#pragma unroll
            for (int i = 0; i < 4; i++) a[i] = As[kk][ty * 4 + i];
#pragma unroll
            for (int j = 0; j < 4; j++) b[j] = Bs[kk][tx * 4 + j];
#pragma unroll
            for (int i = 0; i < 4; i++)
#pragma unroll
                for (int j = 0; j < 4; j++)
                    acc[i][j] += a[i] * b[j];
        }
        __syncthreads();
    }
#pragma unroll
    for (int i = 0; i < 4; i++) {
        int gm = m0 + ty * 4 + i;
        if (gm >= M) continue;
#pragma unroll
        for (int j = 0; j < 4; j++) {
            int gn = n0 + tx * 4 + j;
            if (gn >= N) continue;
            float v = acc[i][j] + bias[gn];
            if (doRelu) v = fmaxf(v, 0.f);
            C[(size_t)gm * ldc + gn] = v;
        }
    }
}

// ---------------- init MLP layer0 ----------------
__global__ void layer0_kernel(const float* __restrict__ kp, const float* __restrict__ W,
                              const float* __restrict__ b, float* __restrict__ out)
{
    int idx = blockIdx.x * blockDim.x + threadIdx.x;
    if (idx >= MKP * 64) return;
    int row = idx >> 6, j = idx & 63;
    const float* x = kp + row * KPD;
    float v = b[j];
#pragma unroll
    for (int i = 0; i < KPD; i++) v += x[i] * W[i * 64 + j];
    out[idx] = fmaxf(v, 0.f);
}

// ---------------- CSR construction ----------------
__global__ void zero_counts_kernel()
{
    int i = blockIdx.x * blockDim.x + threadIdx.x;
    if (i <= NV) g_counts[i] = 0;
}
__global__ void hist_kernel(const int* __restrict__ ei)
{
    int e = blockIdx.x * blockDim.x + threadIdx.x;
    if (e >= NE) return;
    atomicAdd(&g_counts[ei[NE + e]], 1);
}
__global__ void scan_kernel()
{
    __shared__ int sh[1024];
    int t = threadIdx.x;
    const int chunk = (NV + 1023) / 1024;
    int lo = t * chunk, hi = min(NV, lo + chunk);
    int sum = 0;
    for (int i = lo; i < hi; i++) sum += g_counts[i];
    sh[t] = sum;
    __syncthreads();
    for (int off = 1; off < 1024; off <<= 1) {
        int v = (t >= off) ? sh[t - off] : 0;
        __syncthreads();
        sh[t] += v;
        __syncthreads();
    }
    int run = (t == 0) ? 0 : sh[t - 1];
    for (int i = lo; i < hi; i++) {
        g_offs[i] = run;
        g_cursor[i] = run;
        run += g_counts[i];
    }
    if (t == 1023) g_offs[NV] = sh[1023];
}
__global__ void scatter_kernel(const int* __restrict__ ei)
{
    int e = blockIdx.x * blockDim.x + threadIdx.x;
    if (e >= NE) return;
    int dst = ei[NE + e];
    int slot = atomicAdd(&g_cursor[dst], 1);
    g_sortedSrc[slot] = ei[e];
}

// ---------------- fused edge message + segment max ----------------
// u layout: [NV x USTR]; cols 0..299 = s@Wf'+bf, cols 300..302 = dx
#define ECHUNK 64
__global__ void edge_aggr_kernel(const float* __restrict__ u, const float* __restrict__ pos,
                                 const float* __restrict__ Wf3,
                                 float* __restrict__ aggr)
{
    __shared__ float wsh[3 * SD];
    __shared__ float dsh[ECHUNK * 3];
    __shared__ int   ssh[ECHUNK];
    int v = blockIdx.x;
    int t = threadIdx.x;   // 320
    for (int i = t; i < 3 * SD; i += blockDim.x) wsh[i] = Wf3[i];

    float pvx = pos[v * 3 + 0], pvy = pos[v * 3 + 1], pvz = pos[v * 3 + 2];
    float dvx = u[(size_t)v * USTR + 300];
    float dvy = u[(size_t)v * USTR + 301];
    float dvz = u[(size_t)v * USTR + 302];
    int lo = g_offs[v], hi = g_offs[v + 1];
    float best = 0.f;
    __syncthreads();

    for (int c0 = lo; c0 < hi; c0 += ECHUNK) {
        int cnt = min(ECHUNK, hi - c0);
        if (t < cnt) {
            int src = g_sortedSrc[c0 + t];
            ssh[t] = src;
            dsh[t * 3 + 0] = pos[src * 3 + 0] - pvx + dvx;
            dsh[t * 3 + 1] = pos[src * 3 + 1] - pvy + dvy;
            dsh[t * 3 + 2] = pos[src * 3 + 2] - pvz + dvz;
        }
        __syncthreads();
        if (t < SD) {
            float w0 = wsh[t], w1 = wsh[SD + t], w2 = wsh[2 * SD + t];
            for (int j = 0; j < cnt; j++) {
                float c = dsh[j * 3 + 0] * w0 + dsh[j * 3 + 1] * w1 + dsh[j * 3 + 2] * w2;
                float val = u[(size_t)ssh[j] * USTR + t] + c;
                best = fmaxf(best, val);
            }
        }
        __syncthreads();
    }
    if (t < SD) aggr[v * SD + t] = best;
}

// ---------------- host launch ----------------
static inline dim3 mm_grid(int M, int N, int z = 1)
{
    return dim3((N + MBN - 1) / MBN, (M + MBM - 1) / MBM, z);
}

template<typename T>
static T* sym(const void* s) { void* p; cudaGetSymbolAddress(&p, s); return (T*)p; }

extern "C" void kernel_launch(void* const* d_in, const int* in_sizes, int n_in,
                              void* d_out, int out_size)
{
    const float* key_points = (const float*)d_in[0];
    const float* pos        = (const float*)d_in[1];
    const int*   edge_index = (const int*)d_in[3];
    const float* Wi0 = (const float*)d_in[4];   const float* bi0 = (const float*)d_in[5];
    const float* Wi1 = (const float*)d_in[6];   const float* bi1 = (const float*)d_in[7];
    const float* Wi2 = (const float*)d_in[8];   const float* bi2 = (const float*)d_in[9];
    const float* Wa  = (const float*)d_in[10];  const float* ba  = (const float*)d_in[11];
    const float* Wh  = (const float*)d_in[12];  const float* bh  = (const float*)d_in[13];
    const float* Wf  = (const float*)d_in[14];  const float* bf  = (const float*)d_in[15];
    const float* Wg  = (const float*)d_in[16];  const float* bg  = (const float*)d_in[17];
    const float* Wc1 = (const float*)d_in[18];  const float* bc1 = (const float*)d_in[19];
    const float* Wc2 = (const float*)d_in[20];  const float* bc2 = (const float*)d_in[21];
    const float* Wl1 = (const float*)d_in[22];  const float* bl1 = (const float*)d_in[23];
    const float* Wl2 = (const float*)d_in[24];  const float* bl2 = (const float*)d_in[25];
    const float* Wl3 = (const float*)d_in[26];  const float* bl3 = (const float*)d_in[27];

    float* out_cls = (float*)d_out;
    float* out_reg = (float*)d_out + NV * NC;

    float *h0 = sym<float>(g_h0), *h1 = sym<float>(g_h1), *kpmax = sym<float>(g_kpmax);
    float *sA = sym<float>(g_sA), *sB = sym<float>(g_sB), *u = sym<float>(g_u);
    float *aggr = sym<float>(g_aggr), *cbias = sym<float>(g_cbias), *hbias = sym<float>(g_hbias);
    float *l1all = sym<float>(g_l1all), *l2all = sym<float>(g_l2all);
    bf16 *wi1h = sym<bf16>(g_wi1h), *wi1l = sym<bf16>(g_wi1l);
    bf16 *wi2h = sym<bf16>(g_wi2h), *wi2l = sym<bf16>(g_wi2l);
    bf16 *wah = sym<bf16>(g_wah),   *wal = sym<bf16>(g_wal);
    bf16 *wfph = sym<bf16>(g_wfph), *wfpl = sym<bf16>(g_wfpl);
    bf16 *wgh = sym<bf16>(g_wgh),   *wgl = sym<bf16>(g_wgl);
    bf16 *whh = sym<bf16>(g_whh),   *whl = sym<bf16>(g_whl);
    bf16 *wl2h = sym<bf16>(g_wl2h), *wl2l = sym<bf16>(g_wl2l);

    cudaFuncSetAttribute(mma_gemm<0,1,0>, cudaFuncAttributeMaxDynamicSharedMemorySize, MM_SMEM);
    cudaFuncSetAttribute(mma_gemm<1,0,0>, cudaFuncAttributeMaxDynamicSharedMemorySize, MM_SMEM);
    cudaFuncSetAttribute(mma_gemm<0,0,0>, cudaFuncAttributeMaxDynamicSharedMemorySize, MM_SMEM);
    cudaFuncSetAttribute(mma_gemm<0,0,1>, cudaFuncAttributeMaxDynamicSharedMemorySize, MM_SMEM);

    // ---- launch 0: weight splits ----
    {
        SJobs js;
        int j = 0;
        auto add = [&](const float* src, const float* src2, int N2,
                       bf16* dh, bf16* dl, int K, int N, int Kp, int Np) {
            js.src[j] = src; js.src2[j] = src2; js.N2[j] = N2;
            js.dh[j] = dh; js.dl[j] = dl;
            js.K[j] = K; js.N[j] = N; js.Kp[j] = Kp; js.Np[j] = Np; j++;
        };
        add(Wi1, nullptr, 0, wi1h, wi1l, 64, 128, 64, 128);
        add(Wi2, nullptr, 0, wi2h, wi2l, 128, SD, 128, NP3);
        add(Wa,  nullptr, 0, wah,  wal,  SD, SD, SDP, NP3);
        for (int t = 0; t < TIT; t++)
            add(Wf + t * (SD + 3) * SD + 3 * SD, Wh + t * SD * 3, 3,
                wfph + t * SDP * NP3, wfpl + t * SDP * NP3, SD, SD, SDP, NP3);
        for (int t = 0; t < TIT; t++)
            add(Wg + t * SD * SD, nullptr, 0, wgh + t * SDP * NP3, wgl + t * SDP * NP3,
                SD, SD, SDP, NP3);
        // head batch z: 0 = Wc1, 1..4 = Wl1 classes
        add(Wc1, nullptr, 0, whh, whl, SD, 64, SDP, 64);
        for (int c = 0; c < NC; c++)
            add(Wl1 + c * SD * 64, nullptr, 0,
                whh + (1 + c) * SDP * 64, whl + (1 + c) * SDP * 64, SD, 64, SDP, 64);
        for (int c = 0; c < NC; c++)
            add(Wl2 + c * 64 * 64, nullptr, 0, wl2h + c * 64 * 64, wl2l + c * 64 * 64,
                64, 64, 64, 64);
        split_jobs_kernel<<<dim3(64, NJOBS), 256>>>(js);
    }

    // launches 1-2 (so profiled launch index 3 is the kpmax DOMAX GEMM)
    layer0_kernel<<<(MKP * 64 + 255) / 256, 256>>>(key_points, Wi0, bi0, h0);
    mma_gemm<0,1,0><<<mm_grid(MKP, 128), 512, MM_SMEM>>>(
        h0, 64, 0, wi1h, wi1l, 128, 0, bi1, 0, nullptr, h1, 128, 0, MKP, 64, 128);

    // ---- launch 3: kpmax fused GEMM+segment-max (ncu capture target) ----
    mma_gemm<1,0,0><<<mm_grid(MKP, SD), 512, MM_SMEM>>>(
        h1, 128, 0, wi2h, wi2l, NP3, 0, bi2, 0, nullptr, kpmax, SD, 0, MKP, 128, SD);
    mma_gemm<0,1,0><<<mm_grid(NV, SD), 512, MM_SMEM>>>(
        kpmax, SD, 0, wah, wal, NP3, 0, ba, 0, nullptr, sA, SD, 0, NV, SD, SD);

    // ---- combined biases + CSR build ----
    fill_bias_kernel<<<(TIT * NU + 255) / 256, 256>>>(bf, bh, bc1, bl1, cbias, hbias);
    zero_counts_kernel<<<(NV + 256) / 256, 256>>>();
    hist_kernel<<<(NE + 255) / 256, 256>>>(edge_index);
    scan_kernel<<<1, 1024>>>();
    scatter_kernel<<<(NE + 255) / 256, 256>>>(edge_index);

    // ---- GNN iterations (dx fused into u GEMM as cols 300..302) ----
    float* s_cur = sA;
    float* s_nxt = sB;
    for (int t = 0; t < TIT; t++) {
        const float* Wft = Wf + t * (SD + 3) * SD;   // rows 0..2 for edge_aggr
        const float* bgt = bg + t * SD;

        mma_gemm<0,0,0><<<mm_grid(NV, NU), 512, MM_SMEM>>>(
            s_cur, SD, 0, wfph + t * SDP * NP3, wfpl + t * SDP * NP3, NP3, 0,
            cbias + t * NU, 0, nullptr, u, USTR, 0, NV, SD, NU);
        edge_aggr_kernel<<<NV, 320>>>(u, pos, Wft, aggr);
        mma_gemm<0,0,1><<<mm_grid(NV, SD), 512, MM_SMEM>>>(
            aggr, SD, 0, wgh + t * SDP * NP3, wgl + t * SDP * NP3, NP3, 0,
            bgt, 0, s_cur, s_nxt, SD, 0, NV, SD, SD);
        float* tmp = s_cur; s_cur = s_nxt; s_nxt = tmp;
    }

    // ---- heads: c1 + 4x l1 in ONE z=5 launch -> l1all [NV, 320] ----
    mma_gemm<0,1,0><<<mm_grid(NV, 64, NH), 512, MM_SMEM>>>(
        s_cur, SD, 0, whh, whl, 64, (long)SDP * 64, hbias, 64,
        nullptr, l1all, L1STR, 64, NV, SD, 64);
    // cls: out_cls = relu(c1 @ Wc2 + bc2), c1 = l1all cols 0..63
    sgemm_bias<<<dim3(1, (NV + BM - 1) / BM, 1), 256>>>(
        l1all, L1STR, 0, Wc2, 0, bc2, 0, out_cls, 0, NV, 64, NC, NC, 1);
    // l2: per-class from l1all cols 64.. -> l2all [NV, 256]
    mma_gemm<0,1,0><<<mm_grid(NV, 64, NC), 512, MM_SMEM>>>(
        l1all + 64, L1STR, 64, wl2h, wl2l, 64, (long)64 * 64, bl2, 64,
        nullptr, l2all, 256, 64, NV, 64, 64);
    // Wl3 -> out_reg [NV, 28]
    sgemm_bias<<<dim3(1, (NV + BM - 1) / BM, NC), 256>>>(
        l2all, 256, 64, Wl3, (long)64 * 7, bl3, 7, out_reg, 7, NV, 64, 7, NC * 7, 1);
}

// round 17
// speedup vs baseline: 1.0678x; 1.0411x over previous
#include <cuda_runtime.h>
#include <cuda_bf16.h>
#include <cstdint>

// ---------------- problem constants ----------------
#define NV   20000
#define KPV  8
#define MKP  (NV * KPV)
#define NE   320000
#define KPD  4
#define SD   300
#define SDP  320            // K=300 padded to 32-mult
#define NP3  384            // N padded for B (3 x 128 tiles)
#define NU   303            // u GEMM N: 300 (Wf') + 3 (Wh)
#define USTR 320            // u row stride
#define TIT  3
#define NC   4
#define NH   5              // head batch: c1 + 4 classes
#define L1STR 320           // l1all row stride (5 x 64)

typedef __nv_bfloat16 bf16;

// ---------------- scratch ----------------
__device__ float g_h0[MKP * 64];
__device__ float g_h1[MKP * 128];
__device__ float g_kpmax[NV * SD];
__device__ float g_sA[NV * SD];
__device__ float g_sB[NV * SD];
__device__ float g_u[NV * USTR];        // cols 0..299 = u, 300..302 = dx
__device__ float g_aggr[NV * SD];
__device__ float g_l1all[NV * L1STR];   // cols 0..63 = c1, 64.. = l1 per class
__device__ float g_l2all[NV * 256];
__device__ float g_cbias[TIT * NU];     // [bf | bh] per iteration
__device__ float g_hbias[NH * 64];      // [bc1 | bl1(4x64)]
// weight splits (bf16 hi/lo), K padded to 32-mult
__device__ bf16 g_wi1h[64 * 128],        g_wi1l[64 * 128];
__device__ bf16 g_wi2h[128 * NP3],       g_wi2l[128 * NP3];
__device__ bf16 g_wah[SDP * NP3],        g_wal[SDP * NP3];
__device__ bf16 g_wfph[TIT * SDP * NP3], g_wfpl[TIT * SDP * NP3];  // [Wf' | Wh]
__device__ bf16 g_wgh[TIT * SDP * NP3],  g_wgl[TIT * SDP * NP3];
__device__ bf16 g_whh[NH * SDP * 64],    g_whl[NH * SDP * 64];     // [Wc1 | Wl1 x4]
__device__ bf16 g_wl2h[NC * 64 * 64],    g_wl2l[NC * 64 * 64];
// CSR
__device__ int g_counts[NV + 1];
__device__ int g_offs[NV + 1];
__device__ int g_cursor[NV];
__device__ int g_sortedSrc[NE];

// ---------------- helpers ----------------
__device__ __forceinline__ uint32_t smem_u32(const void* p) {
    uint32_t a;
    asm("{ .reg .u64 t; cvta.to.shared.u64 t, %1; cvt.u32.u64 %0, t; }" : "=r"(a) : "l"(p));
    return a;
}
__device__ __forceinline__ void split2(float x, bf16& h, bf16& l) {
    h = __float2bfloat16(x);
    l = __float2bfloat16(x - __bfloat162float(h));
}

#define LDSM_X4(r, addr) \
    asm volatile("ldmatrix.sync.aligned.m8n8.x4.shared.b16 {%0,%1,%2,%3}, [%4];" \
                 : "=r"((r)[0]), "=r"((r)[1]), "=r"((r)[2]), "=r"((r)[3]) : "r"(addr))
#define LDSM_X4T(r, addr) \
    asm volatile("ldmatrix.sync.aligned.m8n8.x4.trans.shared.b16 {%0,%1,%2,%3}, [%4];" \
                 : "=r"((r)[0]), "=r"((r)[1]), "=r"((r)[2]), "=r"((r)[3]) : "r"(addr))
#define MMA_BF16(d, a, b) \
    asm volatile("mma.sync.aligned.m16n8k16.row.col.f32.bf16.bf16.f32 " \
                 "{%0,%1,%2,%3}, {%4,%5,%6,%7}, {%8,%9}, {%0,%1,%2,%3};" \
                 : "+f"((d)[0]), "+f"((d)[1]), "+f"((d)[2]), "+f"((d)[3]) \
                 : "r"((a)[0]), "r"((a)[1]), "r"((a)[2]), "r"((a)[3]), \
                   "r"((b)[0]), "r"((b)[1]))

// =====================================================================
// bf16-split tensor-core GEMM (R13 core, MKC=32 — best measured).
// =====================================================================
#define MBM 128
#define MBN 128
#define MKC 32
#define ASTR 40
#define BSTR 136
#define OA_H 0
#define OA_L 10240
#define OB_H 20480
#define OB_L 29184
#define BUFSZ 37888
#define MM_SMEM (2 * BUFSZ)

template<int DOMAX, int DORELU, int DORES>
__global__ __launch_bounds__(512, 1)
void mma_gemm(const float* __restrict__ A, int lda, long aStr,
              const bf16* __restrict__ Bh, const bf16* __restrict__ Bl,
              int ldb, long bStr,
              const float* __restrict__ bias, int biasStr,
              const float* __restrict__ R,
              float* __restrict__ C, int ldc, long cStr,
              int M, int K, int N)
{
    extern __shared__ char smem[];
    const uint32_t sb = smem_u32(smem);
    const int tid = threadIdx.x, lane = tid & 31, wid = tid >> 5;  // 16 warps
    const int wm = wid & 3, wn = wid >> 2;                          // 4 x 4
    const int m0 = blockIdx.y * MBM, n0 = blockIdx.x * MBN;
    const int z = blockIdx.z;
    A    += (size_t)z * aStr;
    Bh   += (size_t)z * bStr;
    Bl   += (size_t)z * bStr;
    bias += (size_t)z * biasStr;
    C    += (size_t)z * cStr;

    const int nch = (K + MKC - 1) / MKC;
    const bool wact = (n0 + wn * 32) < N;

    float acc[2][4][4];
#pragma unroll
    for (int i = 0; i < 2; i++)
#pragma unroll
        for (int j = 0; j < 4; j++)
#pragma unroll
            for (int k = 0; k < 4; k++) acc[i][j][k] = 0.f;

    float4 pa[2];
    uint4 pbh, pbl;
    const float4 z4 = make_float4(0.f, 0.f, 0.f, 0.f);
    const uint4 zu = make_uint4(0u, 0u, 0u, 0u);

    const int ar = tid >> 2;
    const int akb = (tid & 3) * 8;
    const int bk = tid >> 4;
    const int bc = (tid & 15) * 8;

    auto load_regs = [&](int c) {
        const int k0 = c * MKC;
        const int gm = m0 + ar;
#pragma unroll
        for (int i = 0; i < 2; i++) {
            const int gk = k0 + akb + i * 4;
            pa[i] = (gm < M && gk < K) ? *(const float4*)(A + (size_t)gm * lda + gk) : z4;
        }
        const int gn = n0 + bc;
        const size_t brow = (size_t)(k0 + bk) * ldb;
        if (gn < ldb) {
            pbh = *(const uint4*)(Bh + brow + gn);
            pbl = *(const uint4*)(Bl + brow + gn);
        } else {
            pbh = zu;
            pbl = zu;
        }
    };

    auto store_smem = [&](int buf) {
        const uint32_t bo = buf * BUFSZ;
        const uint32_t abase = bo + (uint32_t)(ar * ASTR + akb) * 2;
#pragma unroll
        for (int i = 0; i < 2; i++) {
            float4 v = pa[i];
            __nv_bfloat162 h01 = __float22bfloat162_rn(make_float2(v.x, v.y));
            __nv_bfloat162 h23 = __float22bfloat162_rn(make_float2(v.z, v.w));
            float2 f01 = __bfloat1622float2(h01);
            float2 f23 = __bfloat1622float2(h23);
            __nv_bfloat162 l01 = __float22bfloat162_rn(make_float2(v.x - f01.x, v.y - f01.y));
            __nv_bfloat162 l23 = __float22bfloat162_rn(make_float2(v.z - f23.x, v.w - f23.y));
            *(__nv_bfloat162*)(smem + OA_H + abase + i * 8)     = h01;
            *(__nv_bfloat162*)(smem + OA_H + abase + i * 8 + 4) = h23;
            *(__nv_bfloat162*)(smem + OA_L + abase + i * 8)     = l01;
            *(__nv_bfloat162*)(smem + OA_L + abase + i * 8 + 4) = l23;
        }
        const uint32_t boff = bo + (uint32_t)(bk * BSTR + bc) * 2;
        *(uint4*)(smem + OB_H + boff) = pbh;
        *(uint4*)(smem + OB_L + boff) = pbl;
    };

    load_regs(0);
    store_smem(0);

    const int arow16 = lane & 15;
    const int hi8 = (lane >> 4) * 8;

    for (int c = 0; c < nch; c++) {
        __syncthreads();
        const int nxt = c + 1;
        if (nxt < nch) load_regs(nxt);

        if (wact) {
            const uint32_t bufo = (uint32_t)(c & 1) * BUFSZ;
            const uint32_t aH = sb + OA_H + bufo;
            const uint32_t aL = sb + OA_L + bufo;
            const uint32_t bH = sb + OB_H + bufo;
            const uint32_t bL = sb + OB_L + bufo;
#pragma unroll
            for (int ks = 0; ks < 2; ks++) {
                uint32_t ah[2][4], al[2][4];
#pragma unroll
                for (int mb = 0; mb < 2; mb++) {
                    const uint32_t ao =
                        (uint32_t)((wm * 32 + mb * 16 + arow16) * ASTR + ks * 16 + hi8) * 2;
                    LDSM_X4(ah[mb], aH + ao);
                    LDSM_X4(al[mb], aL + ao);
                }
                uint32_t bh[4][2], bl[4][2];
#pragma unroll
                for (int nb = 0; nb < 2; nb++) {
                    const uint32_t bo2 =
                        (uint32_t)((ks * 16 + arow16) * BSTR + wn * 32 + nb * 16 + hi8) * 2;
                    uint32_t r[4];
                    LDSM_X4T(r, bH + bo2);
                    bh[nb * 2][0] = r[0]; bh[nb * 2][1] = r[1];
                    bh[nb * 2 + 1][0] = r[2]; bh[nb * 2 + 1][1] = r[3];
                    LDSM_X4T(r, bL + bo2);
                    bl[nb * 2][0] = r[0]; bl[nb * 2][1] = r[1];
                    bl[nb * 2 + 1][0] = r[2]; bl[nb * 2 + 1][1] = r[3];
                }
#pragma unroll
                for (int mb = 0; mb < 2; mb++)
#pragma unroll
                    for (int f = 0; f < 4; f++) {
                        MMA_BF16(acc[mb][f], ah[mb], bh[f]);
                        MMA_BF16(acc[mb][f], al[mb], bh[f]);
                        MMA_BF16(acc[mb][f], ah[mb], bl[f]);
                    }
            }
        }

        if (nxt < nch) store_smem(nxt & 1);
    }

    if (!wact) return;

    // ---- epilogue ----
#pragma unroll
    for (int mb = 0; mb < 2; mb++) {
        const int rbase = m0 + wm * 32 + mb * 16;
#pragma unroll
        for (int f = 0; f < 4; f++) {
            const int cc = n0 + wn * 32 + f * 8 + (lane & 3) * 2;
            float d0 = acc[mb][f][0], d1 = acc[mb][f][1];
            float d2 = acc[mb][f][2], d3 = acc[mb][f][3];
            if (DOMAX) {
                const float b0v = (cc < N) ? bias[cc] : 0.f;
                const float b1v = (cc + 1 < N) ? bias[cc + 1] : 0.f;
                float v0 = fmaxf(d0 + b0v, 0.f), v1 = fmaxf(d1 + b1v, 0.f);
                float v2 = fmaxf(d2 + b0v, 0.f), v3 = fmaxf(d3 + b1v, 0.f);
#pragma unroll
                for (int off = 4; off < 32; off <<= 1) {
                    v0 = fmaxf(v0, __shfl_xor_sync(0xffffffffu, v0, off));
                    v1 = fmaxf(v1, __shfl_xor_sync(0xffffffffu, v1, off));
                    v2 = fmaxf(v2, __shfl_xor_sync(0xffffffffu, v2, off));
                    v3 = fmaxf(v3, __shfl_xor_sync(0xffffffffu, v3, off));
                }
                if ((lane >> 2) == 0 && cc < N) {
                    const int g0 = rbase >> 3, g1 = (rbase + 8) >> 3;
                    C[(size_t)g0 * ldc + cc] = v0;
                    C[(size_t)g1 * ldc + cc] = v2;
                    if (cc + 1 < N) {
                        C[(size_t)g0 * ldc + cc + 1] = v1;
                        C[(size_t)g1 * ldc + cc + 1] = v3;
                    }
                }
            } else {
                const int r = rbase + (lane >> 2);
                if (cc < N) {
                    const float b0v = bias[cc];
                    const float b1v = (cc + 1 < N) ? bias[cc + 1] : 0.f;
                    if (r < M) {
                        float x0 = d0 + b0v, x1 = d1 + b1v;
                        if (DORES) { x0 += R[(size_t)r * ldc + cc]; if (cc + 1 < N) x1 += R[(size_t)r * ldc + cc + 1]; }
                        if (DORELU) { x0 = fmaxf(x0, 0.f); x1 = fmaxf(x1, 0.f); }
                        C[(size_t)r * ldc + cc] = x0;
                        if (cc + 1 < N) C[(size_t)r * ldc + cc + 1] = x1;
                    }
                    if (r + 8 < M) {
                        float x2 = d2 + b0v, x3 = d3 + b1v;
                        if (DORES) { x2 += R[(size_t)(r + 8) * ldc + cc]; if (cc + 1 < N) x3 += R[(size_t)(r + 8) * ldc + cc + 1]; }
                        if (DORELU) { x2 = fmaxf(x2, 0.f); x3 = fmaxf(x3, 0.f); }
                        C[(size_t)(r + 8) * ldc + cc] = x2;
                        if (cc + 1 < N) C[(size_t)(r + 8) * ldc + cc + 1] = x3;
                    }
                }
            }
        }
    }
}

// ---------------- batched weight split (with optional appended src2) ----------------
#define NJOBS 18
struct SJobs {
    const float* src[NJOBS];
    const float* src2[NJOBS];
    bf16* dh[NJOBS];
    bf16* dl[NJOBS];
    int K[NJOBS], N[NJOBS], N2[NJOBS], Kp[NJOBS], Np[NJOBS];
};

__global__ void split_jobs_kernel(SJobs js)
{
    const int job = blockIdx.y;
    const int Np = js.Np[job], K = js.K[job], N = js.N[job], N2 = js.N2[job];
    const int total = js.Kp[job] * Np;
    const float* src = js.src[job];
    const float* src2 = js.src2[job];
    bf16* dh = js.dh[job];
    bf16* dl = js.dl[job];
    for (int idx = blockIdx.x * blockDim.x + threadIdx.x; idx < total;
         idx += gridDim.x * blockDim.x) {
        const int k = idx / Np, n = idx - k * Np;
        float v = 0.f;
        if (k < K) {
            if (n < N) v = src[k * N + n];
            else if (n < N + N2) v = src2[k * N2 + (n - N)];
        }
        bf16 h, l; split2(v, h, l);
        dh[idx] = h;
        dl[idx] = l;
    }
}

// combined biases: [bf | bh] per iteration, and [bc1 | bl1 x4]
__global__ void fill_bias_kernel(const float* __restrict__ bf_, const float* __restrict__ bh_,
                                 const float* __restrict__ bc1_, const float* __restrict__ bl1_,
                                 float* __restrict__ cb, float* __restrict__ hb)
{
    int idx = blockIdx.x * blockDim.x + threadIdx.x;
    if (idx < TIT * NU) {
        int t = idx / NU, n = idx - t * NU;
        cb[idx] = (n < SD) ? bf_[t * SD + n] : bh_[t * 3 + (n - SD)];
    }
    if (idx < NH * 64) {
        hb[idx] = (idx < 64) ? bc1_[idx] : bl1_[idx - 64];
    }
}

// ---------------- small-N generic GEMM (N=4, N=7 heads), z-batched ----------------
#define BM 64
#define BN 64
#define BK 16
__global__ void sgemm_bias(const float* __restrict__ A, int lda, long aStr,
                           const float* __restrict__ B, long bStr,
                           const float* __restrict__ bias, int biasStr,
                           float* __restrict__ C, long cStr,
                           int M, int K, int N, int ldc, int doRelu)
{
    __shared__ float As[BK][BM + 1];
    __shared__ float Bs[BK][BN];
    int tid = threadIdx.x;
    int tx = tid & 15, ty = tid >> 4;
    int m0 = blockIdx.y * BM, n0 = blockIdx.x * BN;
    const int z = blockIdx.z;
    A    += (size_t)z * aStr;
    B    += (size_t)z * bStr;
    bias += (size_t)z * biasStr;
    C    += (size_t)z * cStr;
    float acc[4][4] = {};

    for (int k0 = 0; k0 < K; k0 += BK) {
        {
            int m  = tid >> 2;
            int kb = (tid & 3) * 4;
            int gm = m0 + m;
#pragma unroll
            for (int i = 0; i < 4; i++) {
                int kk = kb + i, gk = k0 + kk;
                As[kk][m] = (gm < M && gk < K) ? A[(size_t)gm * lda + gk] : 0.f;
            }
        }
        {
            int kk = tid >> 4;
            int nb = (tid & 15) * 4;
            int gk = k0 + kk;
#pragma unroll
            for (int i = 0; i < 4; i++) {
                int n = nb + i, gn = n0 + n;
                Bs[kk][n] = (gk < K && gn < N) ? B[(size_t)gk * N + gn] : 0.f;
            }
        }
        __syncthreads();
#pragma unroll
        for (int kk = 0; kk < BK; kk++) {
            float a[4], b[4];
#pragma unroll
            for (int i = 0; i < 4; i++) a[i] = As[kk][ty * 4 + i];
#pragma unroll
            for (int j = 0; j < 4; j++) b[j] = Bs[kk][tx * 4 + j];
#pragma unroll
            for (int i = 0; i < 4; i++)
#pragma unroll
                for (int j = 0; j < 4; j++)
                    acc[i][j] += a[i] * b[j];
        }
        __syncthreads();
    }
#pragma unroll
    for (int i = 0; i < 4; i++) {
        int gm = m0 + ty * 4 + i;
        if (gm >= M) continue;
#pragma unroll
        for (int j = 0; j < 4; j++) {
            int gn = n0 + tx * 4 + j;
            if (gn >= N) continue;
            float v = acc[i][j] + bias[gn];
            if (doRelu) v = fmaxf(v, 0.f);
            C[(size_t)gm * ldc + gn] = v;
        }
    }
}

// ---------------- init MLP layer0 ----------------
__global__ void layer0_kernel(const float* __restrict__ kp, const float* __restrict__ W,
                              const float* __restrict__ b, float* __restrict__ out)
{
    int idx = blockIdx.x * blockDim.x + threadIdx.x;
    if (idx >= MKP * 64) return;
    int row = idx >> 6, j = idx & 63;
    const float* x = kp + row * KPD;
    float v = b[j];
#pragma unroll
    for (int i = 0; i < KPD; i++) v += x[i] * W[i * 64 + j];
    out[idx] = fmaxf(v, 0.f);
}

// ---------------- CSR construction ----------------
__global__ void zero_counts_kernel()
{
    int i = blockIdx.x * blockDim.x + threadIdx.x;
    if (i <= NV) g_counts[i] = 0;
}
__global__ void hist_kernel(const int* __restrict__ ei)
{
    int e = blockIdx.x * blockDim.x + threadIdx.x;
    if (e >= NE) return;
    atomicAdd(&g_counts[ei[NE + e]], 1);
}
__global__ void scan_kernel()
{
    __shared__ int sh[1024];
    int t = threadIdx.x;
    const int chunk = (NV + 1023) / 1024;
    int lo = t * chunk, hi = min(NV, lo + chunk);
    int sum = 0;
    for (int i = lo; i < hi; i++) sum += g_counts[i];
    sh[t] = sum;
    __syncthreads();
    for (int off = 1; off < 1024; off <<= 1) {
        int v = (t >= off) ? sh[t - off] : 0;
        __syncthreads();
        sh[t] += v;
        __syncthreads();
    }
    int run = (t == 0) ? 0 : sh[t - 1];
    for (int i = lo; i < hi; i++) {
        g_offs[i] = run;
        g_cursor[i] = run;
        run += g_counts[i];
    }
    if (t == 1023) g_offs[NV] = sh[1023];
}
__global__ void scatter_kernel(const int* __restrict__ ei)
{
    int e = blockIdx.x * blockDim.x + threadIdx.x;
    if (e >= NE) return;
    int dst = ei[NE + e];
    int slot = atomicAdd(&g_cursor[dst], 1);
    g_sortedSrc[slot] = ei[e];
}

// ---------------- fused edge message + segment max ----------------
// u layout: [NV x USTR]; cols 0..299 = s@Wf'+bf, cols 300..302 = dx
#define ECHUNK 64
__global__ void edge_aggr_kernel(const float* __restrict__ u, const float* __restrict__ pos,
                                 const float* __restrict__ Wf3,
                                 float* __restrict__ aggr)
{
    __shared__ float wsh[3 * SD];
    __shared__ float dsh[ECHUNK * 3];
    __shared__ int   ssh[ECHUNK];
    int v = blockIdx.x;
    int t = threadIdx.x;   // 320
    for (int i = t; i < 3 * SD; i += blockDim.x) wsh[i] = Wf3[i];

    float pvx = pos[v * 3 + 0], pvy = pos[v * 3 + 1], pvz = pos[v * 3 + 2];
    float dvx = u[(size_t)v * USTR + 300];
    float dvy = u[(size_t)v * USTR + 301];
    float dvz = u[(size_t)v * USTR + 302];
    int lo = g_offs[v], hi = g_offs[v + 1];
    float best = 0.f;
    __syncthreads();

    for (int c0 = lo; c0 < hi; c0 += ECHUNK) {
        int cnt = min(ECHUNK, hi - c0);
        if (t < cnt) {
            int src = g_sortedSrc[c0 + t];
            ssh[t] = src;
            dsh[t * 3 + 0] = pos[src * 3 + 0] - pvx + dvx;
            dsh[t * 3 + 1] = pos[src * 3 + 1] - pvy + dvy;
            dsh[t * 3 + 2] = pos[src * 3 + 2] - pvz + dvz;
        }
        __syncthreads();
        if (t < SD) {
            float w0 = wsh[t], w1 = wsh[SD + t], w2 = wsh[2 * SD + t];
            for (int j = 0; j < cnt; j++) {
                float c = dsh[j * 3 + 0] * w0 + dsh[j * 3 + 1] * w1 + dsh[j * 3 + 2] * w2;
                float val = u[(size_t)ssh[j] * USTR + t] + c;
                best = fmaxf(best, val);
            }
        }
        __syncthreads();
    }
    if (t < SD) aggr[v * SD + t] = best;
}

// ---------------- host launch ----------------
static inline dim3 mm_grid(int M, int N, int z = 1)
{
    return dim3((N + MBN - 1) / MBN, (M + MBM - 1) / MBM, z);
}

template<typename T>
static T* sym(const void* s) { void* p; cudaGetSymbolAddress(&p, s); return (T*)p; }

extern "C" void kernel_launch(void* const* d_in, const int* in_sizes, int n_in,
                              void* d_out, int out_size)
{
    const float* key_points = (const float*)d_in[0];
    const float* pos        = (const float*)d_in[1];
    const int*   edge_index = (const int*)d_in[3];
    const float* Wi0 = (const float*)d_in[4];   const float* bi0 = (const float*)d_in[5];
    const float* Wi1 = (const float*)d_in[6];   const float* bi1 = (const float*)d_in[7];
    const float* Wi2 = (const float*)d_in[8];   const float* bi2 = (const float*)d_in[9];
    const float* Wa  = (const float*)d_in[10];  const float* ba  = (const float*)d_in[11];
    const float* Wh  = (const float*)d_in[12];  const float* bh  = (const float*)d_in[13];
    const float* Wf  = (const float*)d_in[14];  const float* bf  = (const float*)d_in[15];
    const float* Wg  = (const float*)d_in[16];  const float* bg  = (const float*)d_in[17];
    const float* Wc1 = (const float*)d_in[18];  const float* bc1 = (const float*)d_in[19];
    const float* Wc2 = (const float*)d_in[20];  const float* bc2 = (const float*)d_in[21];
    const float* Wl1 = (const float*)d_in[22];  const float* bl1 = (const float*)d_in[23];
    const float* Wl2 = (const float*)d_in[24];  const float* bl2 = (const float*)d_in[25];
    const float* Wl3 = (const float*)d_in[26];  const float* bl3 = (const float*)d_in[27];

    float* out_cls = (float*)d_out;
    float* out_reg = (float*)d_out + NV * NC;

    float *h0 = sym<float>(g_h0), *h1 = sym<float>(g_h1), *kpmax = sym<float>(g_kpmax);
    float *sA = sym<float>(g_sA), *sB = sym<float>(g_sB), *u = sym<float>(g_u);
    float *aggr = sym<float>(g_aggr), *cbias = sym<float>(g_cbias), *hbias = sym<float>(g_hbias);
    float *l1all = sym<float>(g_l1all), *l2all = sym<float>(g_l2all);
    bf16 *wi1h = sym<bf16>(g_wi1h), *wi1l = sym<bf16>(g_wi1l);
    bf16 *wi2h = sym<bf16>(g_wi2h), *wi2l = sym<bf16>(g_wi2l);
    bf16 *wah = sym<bf16>(g_wah),   *wal = sym<bf16>(g_wal);
    bf16 *wfph = sym<bf16>(g_wfph), *wfpl = sym<bf16>(g_wfpl);
    bf16 *wgh = sym<bf16>(g_wgh),   *wgl = sym<bf16>(g_wgl);
    bf16 *whh = sym<bf16>(g_whh),   *whl = sym<bf16>(g_whl);
    bf16 *wl2h = sym<bf16>(g_wl2h), *wl2l = sym<bf16>(g_wl2l);

    cudaFuncSetAttribute(mma_gemm<0,1,0>, cudaFuncAttributeMaxDynamicSharedMemorySize, MM_SMEM);
    cudaFuncSetAttribute(mma_gemm<1,0,0>, cudaFuncAttributeMaxDynamicSharedMemorySize, MM_SMEM);
    cudaFuncSetAttribute(mma_gemm<0,0,0>, cudaFuncAttributeMaxDynamicSharedMemorySize, MM_SMEM);
    cudaFuncSetAttribute(mma_gemm<0,0,1>, cudaFuncAttributeMaxDynamicSharedMemorySize, MM_SMEM);

    // ---- side stream + events: created once on first (non-capture) call ----
    static cudaStream_t s2 = nullptr;
    static cudaEvent_t evF1, evSplit, evCSR, evF2, evCls;
    if (!s2) {
        cudaStreamCreateWithFlags(&s2, cudaStreamNonBlocking);
        cudaEventCreateWithFlags(&evF1,    cudaEventDisableTiming);
        cudaEventCreateWithFlags(&evSplit, cudaEventDisableTiming);
        cudaEventCreateWithFlags(&evCSR,   cudaEventDisableTiming);
        cudaEventCreateWithFlags(&evF2,    cudaEventDisableTiming);
        cudaEventCreateWithFlags(&evCls,   cudaEventDisableTiming);
    }

    // ---- fork: s2 handles weight splits + CSR build + bias fill ----
    cudaEventRecord(evF1, 0);
    cudaStreamWaitEvent(s2, evF1, 0);

    {
        SJobs js;
        int j = 0;
        auto add = [&](const float* src, const float* src2, int N2,
                       bf16* dh, bf16* dl, int K, int N, int Kp, int Np) {
            js.src[j] = src; js.src2[j] = src2; js.N2[j] = N2;
            js.dh[j] = dh; js.dl[j] = dl;
            js.K[j] = K; js.N[j] = N; js.Kp[j] = Kp; js.Np[j] = Np; j++;
        };
        add(Wi1, nullptr, 0, wi1h, wi1l, 64, 128, 64, 128);
        add(Wi2, nullptr, 0, wi2h, wi2l, 128, SD, 128, NP3);
        add(Wa,  nullptr, 0, wah,  wal,  SD, SD, SDP, NP3);
        for (int t = 0; t < TIT; t++)
            add(Wf + t * (SD + 3) * SD + 3 * SD, Wh + t * SD * 3, 3,
                wfph + t * SDP * NP3, wfpl + t * SDP * NP3, SD, SD, SDP, NP3);
        for (int t = 0; t < TIT; t++)
            add(Wg + t * SD * SD, nullptr, 0, wgh + t * SDP * NP3, wgl + t * SDP * NP3,
                SD, SD, SDP, NP3);
        add(Wc1, nullptr, 0, whh, whl, SD, 64, SDP, 64);
        for (int c = 0; c < NC; c++)
            add(Wl1 + c * SD * 64, nullptr, 0,
                whh + (1 + c) * SDP * 64, whl + (1 + c) * SDP * 64, SD, 64, SDP, 64);
        for (int c = 0; c < NC; c++)
            add(Wl2 + c * 64 * 64, nullptr, 0, wl2h + c * 64 * 64, wl2l + c * 64 * 64,
                64, 64, 64, 64);
        split_jobs_kernel<<<dim3(64, NJOBS), 256, 0, s2>>>(js);
    }
    cudaEventRecord(evSplit, s2);

    // main: layer0 (independent of splits)
    layer0_kernel<<<(MKP * 64 + 255) / 256, 256>>>(key_points, Wi0, bi0, h0);
    cudaStreamWaitEvent(0, evSplit, 0);
    mma_gemm<0,1,0><<<mm_grid(MKP, 128), 512, MM_SMEM>>>(
        h0, 64, 0, wi1h, wi1l, 128, 0, bi1, 0, nullptr, h1, 128, 0, MKP, 64, 128);
    // kpmax fused GEMM+segment-max (4th kernel submitted -> ncu capture target)
    mma_gemm<1,0,0><<<mm_grid(MKP, SD), 512, MM_SMEM>>>(
        h1, 128, 0, wi2h, wi2l, NP3, 0, bi2, 0, nullptr, kpmax, SD, 0, MKP, 128, SD);

    // s2 (concurrent with init GEMMs): CSR build + bias fill
    zero_counts_kernel<<<(NV + 256) / 256, 256, 0, s2>>>();
    hist_kernel<<<(NE + 255) / 256, 256, 0, s2>>>(edge_index);
    scan_kernel<<<1, 1024, 0, s2>>>();
    scatter_kernel<<<(NE + 255) / 256, 256, 0, s2>>>(edge_index);
    fill_bias_kernel<<<(TIT * NU + 255) / 256, 256, 0, s2>>>(bf, bh, bc1, bl1, cbias, hbias);
    cudaEventRecord(evCSR, s2);

    // main: sA
    mma_gemm<0,1,0><<<mm_grid(NV, SD), 512, MM_SMEM>>>(
        kpmax, SD, 0, wah, wal, NP3, 0, ba, 0, nullptr, sA, SD, 0, NV, SD, SD);

    // join CSR before GNN loop
    cudaStreamWaitEvent(0, evCSR, 0);

    // ---- GNN iterations (dx fused into u GEMM as cols 300..302) ----
    float* s_cur = sA;
    float* s_nxt = sB;
    for (int t = 0; t < TIT; t++) {
        const float* Wft = Wf + t * (SD + 3) * SD;   // rows 0..2 for edge_aggr
        const float* bgt = bg + t * SD;

        mma_gemm<0,0,0><<<mm_grid(NV, NU), 512, MM_SMEM>>>(
            s_cur, SD, 0, wfph + t * SDP * NP3, wfpl + t * SDP * NP3, NP3, 0,
            cbias + t * NU, 0, nullptr, u, USTR, 0, NV, SD, NU);
        edge_aggr_kernel<<<NV, 320>>>(u, pos, Wft, aggr);
        mma_gemm<0,0,1><<<mm_grid(NV, SD), 512, MM_SMEM>>>(
            aggr, SD, 0, wgh + t * SDP * NP3, wgl + t * SDP * NP3, NP3, 0,
            bgt, 0, s_cur, s_nxt, SD, 0, NV, SD, SD);
        float* tmp = s_cur; s_cur = s_nxt; s_nxt = tmp;
    }

    // ---- heads: c1 + 4x l1 in one z=5 launch -> l1all [NV, 320] ----
    mma_gemm<0,1,0><<<mm_grid(NV, 64, NH), 512, MM_SMEM>>>(
        s_cur, SD, 0, whh, whl, 64, (long)SDP * 64, hbias, 64,
        nullptr, l1all, L1STR, 64, NV, SD, 64);

    // fork: cls head on s2, loc chain on main
    cudaEventRecord(evF2, 0);
    cudaStreamWaitEvent(s2, evF2, 0);
    sgemm_bias<<<dim3(1, (NV + BM - 1) / BM, 1), 256, 0, s2>>>(
        l1all, L1STR, 0, Wc2, 0, bc2, 0, out_cls, 0, NV, 64, NC, NC, 1);
    cudaEventRecord(evCls, s2);

    mma_gemm<0,1,0><<<mm_grid(NV, 64, NC), 512, MM_SMEM>>>(
        l1all + 64, L1STR, 64, wl2h, wl2l, 64, (long)64 * 64, bl2, 64,
        nullptr, l2all, 256, 64, NV, 64, 64);
    sgemm_bias<<<dim3(1, (NV + BM - 1) / BM, NC), 256>>>(
        l2all, 256, 64, Wl3, (long)64 * 7, bl3, 7, out_reg, 7, NV, 64, 7, NC * 7, 1);

    // join cls head
    cudaStreamWaitEvent(0, evCls, 0);
}